// round 12
// baseline (speedup 1.0000x reference)
#include <cuda_runtime.h>
#include <cuda_fp16.h>
#include <cstdint>
#include <math.h>

#define T_TOK 16384
#define DIMN  1024
#define HIDN  2048
#define NE    8

#define BKF   64     // fp16 elements of K per stage
#define PADU  36     // smem row stride in u32 (32 payload + 4 pad)
#define NSTG  3

// ============================ helpers ============================
#define CP_ASYNC16(dst, src) asm volatile("cp.async.cg.shared.global [%0], [%1], 16;" :: "r"(dst), "l"(src))
#define CP_COMMIT()          asm volatile("cp.async.commit_group;" ::: "memory")
#define CP_WAIT(n)           asm volatile("cp.async.wait_group %0;" :: "n"(n) : "memory")

#define LDSM_X4(r0, r1, r2, r3, addr) \
    asm volatile("ldmatrix.sync.aligned.m8n8.x4.shared.b16 {%0,%1,%2,%3}, [%4];" \
        : "=r"(r0), "=r"(r1), "=r"(r2), "=r"(r3) : "r"(addr))

__device__ __forceinline__ uint32_t smem_u32(const void* p) {
    uint32_t a;
    asm("{ .reg .u64 t; cvta.to.shared.u64 t, %1; cvt.u32.u64 %0, t; }" : "=r"(a) : "l"(p));
    return a;
}
__device__ __forceinline__ uint32_t pack_h2(float lo, float hi) {
    __half2 h = __floats2half2_rn(lo, hi);
    return *reinterpret_cast<uint32_t*>(&h);
}
__device__ __forceinline__ void mma_f16(float* c, const uint32_t* a, const uint32_t* b) {
    asm volatile(
        "mma.sync.aligned.m16n8k16.row.col.f32.f16.f16.f32 "
        "{%0,%1,%2,%3}, {%4,%5,%6,%7}, {%8,%9}, {%0,%1,%2,%3};"
        : "+f"(c[0]), "+f"(c[1]), "+f"(c[2]), "+f"(c[3])
        : "r"(a[0]), "r"(a[1]), "r"(a[2]), "r"(a[3]), "r"(b[0]), "r"(b[1]));
}

// ============================ device scratch (fixed-capacity dispatch) ============================
__device__ int      g_count[NE];
__device__ float    g_wt  [NE * T_TOK];
__device__ int      g_slot[T_TOK * 2];
__device__ uint32_t g_Xh [(size_t)NE * T_TOK * DIMN / 2];   // fp16 pairs, capacity slots
__device__ uint32_t g_Hh [(size_t)NE * T_TOK * HIDN / 2];   // fp16 pairs
__device__ float    g_P  [(size_t)NE * T_TOK * DIMN];       // fp32 partials
__device__ uint32_t g_w1h[(size_t)NE * HIDN * DIMN / 2];    // fp16 pairs [e][n][k/2]
__device__ uint32_t g_w3h[(size_t)NE * HIDN * DIMN / 2];
__device__ uint32_t g_w2h[(size_t)NE * DIMN * HIDN / 2];    // transposed [e][n(dim)][k(hid)/2]

// ============================ 1: fused weight conversion (+count reset) ============================
__global__ void convw_kernel(const float* __restrict__ w1, const float* __restrict__ w2,
                             const float* __restrict__ w3) {
    if (blockIdx.x == 0 && threadIdx.x < NE) g_count[threadIdx.x] = 0;

    if (blockIdx.x < 8192) {
        size_t idx = (size_t)blockIdx.x * 256 + threadIdx.x;
        size_t o = idx * 8;
        {
            float4 v0 = *reinterpret_cast<const float4*>(&w1[o]);
            float4 v1 = *reinterpret_cast<const float4*>(&w1[o + 4]);
            uint4 u;
            u.x = pack_h2(v0.x, v0.y); u.y = pack_h2(v0.z, v0.w);
            u.z = pack_h2(v1.x, v1.y); u.w = pack_h2(v1.z, v1.w);
            *reinterpret_cast<uint4*>(&g_w1h[o / 2]) = u;
        }
        {
            float4 v0 = *reinterpret_cast<const float4*>(&w3[o]);
            float4 v1 = *reinterpret_cast<const float4*>(&w3[o + 4]);
            uint4 u;
            u.x = pack_h2(v0.x, v0.y); u.y = pack_h2(v0.z, v0.w);
            u.z = pack_h2(v1.x, v1.y); u.w = pack_h2(v1.z, v1.w);
            *reinterpret_cast<uint4*>(&g_w3h[o / 2]) = u;
        }
    } else {
        __shared__ float tile[32][33];
        int b2 = blockIdx.x - 8192;
        int e = b2 >> 11;
        int rem = b2 & 2047;
        int k0 = (rem >> 5) * 32;
        int n0 = (rem & 31) * 32;
        int tx = threadIdx.x & 31, ty = threadIdx.x >> 5;
        const float* wp = w2 + (size_t)e * HIDN * DIMN;
#pragma unroll
        for (int i = 0; i < 4; i++)
            tile[ty + 8 * i][tx] = wp[(size_t)(k0 + ty + 8 * i) * DIMN + n0 + tx];
        __syncthreads();
        int row = threadIdx.x >> 3;
        int cu = threadIdx.x & 7;
        uint32_t* op = &g_w2h[((size_t)e * DIMN + n0 + row) * (HIDN / 2) + k0 / 2];
#pragma unroll
        for (int jj = 0; jj < 2; jj++) {
            int j = cu * 2 + jj;
            op[j] = pack_h2(tile[2 * j][row], tile[2 * j + 1][row]);
        }
    }
}

// ============================ 2: gate ============================
__global__ void gate_kernel(const float* __restrict__ x, const float* __restrict__ wg) {
    int warp = threadIdx.x >> 5, lane = threadIdx.x & 31;
    int t = blockIdx.x * 8 + warp;
    if (t >= T_TOK) return;
    float acc[NE];
#pragma unroll
    for (int e = 0; e < NE; e++) acc[e] = 0.f;
    const float* xr = x + (size_t)t * DIMN;
    for (int d = lane; d < DIMN; d += 32) {
        float xv = xr[d];
#pragma unroll
        for (int e = 0; e < NE; e++) acc[e] += xv * wg[d * NE + e];
    }
#pragma unroll
    for (int e = 0; e < NE; e++)
#pragma unroll
        for (int o = 16; o > 0; o >>= 1) acc[e] += __shfl_xor_sync(0xffffffffu, acc[e], o);
    if (lane == 0) {
        int i0 = 0; float l0 = acc[0];
#pragma unroll
        for (int e = 1; e < NE; e++) if (acc[e] > l0) { l0 = acc[e]; i0 = e; }
        int i1 = -1; float l1 = -3.0e38f;
#pragma unroll
        for (int e = 0; e < NE; e++) if (e != i0 && acc[e] > l1) { l1 = acc[e]; i1 = e; }
        float w0 = 1.f / (1.f + expf(l1 - l0));
        int p0 = atomicAdd(&g_count[i0], 1);
        int s0 = i0 * T_TOK + p0;
        g_wt[s0] = w0;
        g_slot[2 * t] = s0;
        int p1 = atomicAdd(&g_count[i1], 1);
        int s1 = i1 * T_TOK + p1;
        g_wt[s1] = 1.f - w0;
        g_slot[2 * t + 1] = s1;
    }
}

// ============================ 3: gather ============================
__global__ void gather_kernel(const float* __restrict__ x) {
    size_t idx = (size_t)blockIdx.x * blockDim.x + threadIdx.x;
    if (idx >= (size_t)T_TOK * 2 * (DIMN / 8)) return;
    int a = (int)(idx / (DIMN / 8));
    int g = (int)(idx % (DIMN / 8)) * 8;
    int t = a >> 1, j = a & 1;
    int s = g_slot[2 * t + j];
    const float* sp = &x[(size_t)t * DIMN + g];
    float4 v0 = *reinterpret_cast<const float4*>(sp);
    float4 v1 = *reinterpret_cast<const float4*>(sp + 4);
    uint4 o;
    o.x = pack_h2(v0.x, v0.y); o.y = pack_h2(v0.z, v0.w);
    o.z = pack_h2(v1.x, v1.y); o.w = pack_h2(v1.z, v1.w);
    *reinterpret_cast<uint4*>(&g_Xh[(size_t)s * (DIMN / 2) + g / 2]) = o;
}

// ============================ 4: ffn1  H = silu(X W1^T) * (X W3^T) ============================
// BM=128 BN=64 BK=64. 256 threads, 8 warps 4(m)x2(n); warp tile 32x32 dual. ldmatrix.
__global__ void __launch_bounds__(256, 2) ffn1_kernel() {
    int e = blockIdx.z;
    int cnt = g_count[e];
    int mb = blockIdx.y;
    if (mb * 128 >= cnt) return;
    int base = e * T_TOK + mb * 128;
    int n0 = blockIdx.x * 64;

    extern __shared__ uint32_t smem[];
    uint32_t* As  = smem;                        // [NSTG][128*PADU]
    uint32_t* B1s = As  + NSTG * 128 * PADU;     // [NSTG][64*PADU]
    uint32_t* B3s = B1s + NSTG * 64 * PADU;      // [NSTG][64*PADU]
    const int A_STG = 128 * PADU, B_STG = 64 * PADU;

    int tid = threadIdx.x, wid = tid >> 5, lane = tid & 31;
    int wm = wid & 3, wn = wid >> 2;
    int q = lane >> 2, t4 = lane & 3;

    // cp.async loaders: 2 threads/row, each 16 u32 (64B) of the 32-u32 row
    int arowL = tid >> 1, apart = tid & 1;
    const uint32_t* srcA0 = g_Xh + (size_t)(base + arowL) * (DIMN / 2) + apart * 16;
    uint32_t dstA0 = smem_u32(&As[arowL * PADU + apart * 16]);

    int browL = (tid & 127) >> 1, bpart = tid & 1, bmat = tid >> 7;
    const uint32_t* srcB0 = (bmat ? g_w3h : g_w1h)
        + ((size_t)e * HIDN + n0 + browL) * (DIMN / 2) + bpart * 16;
    uint32_t dstB0 = smem_u32((bmat ? B3s : B1s) + browL * PADU + bpart * 16);

    // ldmatrix per-lane base addresses
    uint32_t aBase = smem_u32(As) + (((wm * 32 + (lane & 15)) * PADU) + (lane >> 4) * 4) * 4;
    uint32_t bRow = wn * 32 + (lane & 7) + ((lane >> 4) & 1) * 8;
    uint32_t bCol = ((lane >> 3) & 1) * 4;
    uint32_t b1Base = smem_u32(B1s) + ((bRow * PADU) + bCol) * 4;
    uint32_t b3Base = smem_u32(B3s) + ((bRow * PADU) + bCol) * 4;

    float acc1[2][4][4], acc3[2][4][4];
#pragma unroll
    for (int i = 0; i < 2; i++)
#pragma unroll
        for (int j = 0; j < 4; j++)
#pragma unroll
            for (int v = 0; v < 4; v++) { acc1[i][j][v] = 0.f; acc3[i][j][v] = 0.f; }

    auto issue = [&](int s, int kc) {
        uint32_t aoff = (uint32_t)(s * A_STG * 4);
        uint32_t boff = (uint32_t)(s * B_STG * 4);
        const uint32_t* sa = srcA0 + kc * 32;
        CP_ASYNC16(dstA0 + aoff,      sa);
        CP_ASYNC16(dstA0 + aoff + 16, sa + 4);
        CP_ASYNC16(dstA0 + aoff + 32, sa + 8);
        CP_ASYNC16(dstA0 + aoff + 48, sa + 12);
        const uint32_t* sb = srcB0 + kc * 32;
        CP_ASYNC16(dstB0 + boff,      sb);
        CP_ASYNC16(dstB0 + boff + 16, sb + 4);
        CP_ASYNC16(dstB0 + boff + 32, sb + 8);
        CP_ASYNC16(dstB0 + boff + 48, sb + 12);
        CP_COMMIT();
    };

    const int KT = DIMN / BKF;   // 16
    issue(0, 0); issue(1, 1);

    int stg = 0;
    for (int kt = 0; kt < KT; kt++) {
        CP_WAIT(1);
        __syncthreads();
        if (kt + 2 < KT) {
            int s = stg + 2; if (s >= NSTG) s -= NSTG;
            issue(s, kt + 2);
        }

        uint32_t sA = aBase + stg * A_STG * 4;
        uint32_t sB1 = b1Base + stg * B_STG * 4;
        uint32_t sB3 = b3Base + stg * B_STG * 4;
#pragma unroll
        for (int kk = 0; kk < 4; kk++) {
            uint32_t koff = kk * 32;   // 8 u32 per k16 step
            uint32_t a[2][4];
#pragma unroll
            for (int i = 0; i < 2; i++)
                LDSM_X4(a[i][0], a[i][1], a[i][2], a[i][3],
                        sA + i * (16 * PADU * 4) + koff);
            uint32_t b1v[2][4], b3v[2][4];
#pragma unroll
            for (int jp = 0; jp < 2; jp++) {
                LDSM_X4(b1v[jp][0], b1v[jp][1], b1v[jp][2], b1v[jp][3],
                        sB1 + jp * (16 * PADU * 4) + koff);
                LDSM_X4(b3v[jp][0], b3v[jp][1], b3v[jp][2], b3v[jp][3],
                        sB3 + jp * (16 * PADU * 4) + koff);
            }
#pragma unroll
            for (int i = 0; i < 2; i++)
#pragma unroll
                for (int j = 0; j < 4; j++) {
                    mma_f16(acc1[i][j], a[i], &b1v[j >> 1][(j & 1) * 2]);
                    mma_f16(acc3[i][j], a[i], &b3v[j >> 1][(j & 1) * 2]);
                }
        }
        if (++stg >= NSTG) stg = 0;
    }
    CP_WAIT(0);

    // epilogue
#pragma unroll
    for (int i = 0; i < 2; i++) {
#pragma unroll
        for (int half = 0; half < 2; half++) {
            int rloc = wm * 32 + i * 16 + q + half * 8;
            if (mb * 128 + rloc < cnt) {
                uint32_t* hrow = g_Hh + (size_t)(base + rloc) * (HIDN / 2) + n0 / 2;
#pragma unroll
                for (int j = 0; j < 4; j++) {
                    int cl = wn * 32 + j * 8 + t4 * 2;
                    float z0 = acc1[i][j][half * 2 + 0];
                    float z1 = acc1[i][j][half * 2 + 1];
                    float h0 = z0 / (1.f + __expf(-z0)) * acc3[i][j][half * 2 + 0];
                    float h1 = z1 / (1.f + __expf(-z1)) * acc3[i][j][half * 2 + 1];
                    hrow[cl / 2] = pack_h2(h0, h1);
                }
            }
        }
    }
}

// ============================ 5: ffn2  P = H W2 ============================
// BM=128 BN=128 BK=64. 256 threads, 8 warps 4(m)x2(n); warp tile 32x64. ldmatrix.
__global__ void __launch_bounds__(256, 2) ffn2_kernel() {
    int e = blockIdx.z;
    int cnt = g_count[e];
    int mb = blockIdx.y;
    if (mb * 128 >= cnt) return;
    int base = e * T_TOK + mb * 128;
    int n0 = blockIdx.x * 128;

    extern __shared__ uint32_t smem[];
    uint32_t* As = smem;                         // [NSTG][128*PADU]
    uint32_t* Bs = As + NSTG * 128 * PADU;       // [NSTG][128*PADU]
    const int A_STG = 128 * PADU, B_STG = 128 * PADU;

    int tid = threadIdx.x, wid = tid >> 5, lane = tid & 31;
    int wm = wid & 3, wn = wid >> 2;
    int q = lane >> 2, t4 = lane & 3;

    int arowL = tid >> 1, apart = tid & 1;
    const uint32_t* srcA0 = g_Hh + (size_t)(base + arowL) * (HIDN / 2) + apart * 16;
    uint32_t dstA0 = smem_u32(&As[arowL * PADU + apart * 16]);

    int browL = tid >> 1, bpart = tid & 1;
    const uint32_t* srcB0 = g_w2h + ((size_t)e * DIMN + n0 + browL) * (HIDN / 2) + bpart * 16;
    uint32_t dstB0 = smem_u32(&Bs[browL * PADU + bpart * 16]);

    uint32_t aBase = smem_u32(As) + (((wm * 32 + (lane & 15)) * PADU) + (lane >> 4) * 4) * 4;
    uint32_t bRow = wn * 64 + (lane & 7) + ((lane >> 4) & 1) * 8;
    uint32_t bCol = ((lane >> 3) & 1) * 4;
    uint32_t bBase = smem_u32(Bs) + ((bRow * PADU) + bCol) * 4;

    float acc[2][8][4];
#pragma unroll
    for (int i = 0; i < 2; i++)
#pragma unroll
        for (int j = 0; j < 8; j++)
#pragma unroll
            for (int v = 0; v < 4; v++) acc[i][j][v] = 0.f;

    auto issue = [&](int s, int kc) {
        uint32_t aoff = (uint32_t)(s * A_STG * 4);
        uint32_t boff = (uint32_t)(s * B_STG * 4);
        const uint32_t* sa = srcA0 + kc * 32;
        CP_ASYNC16(dstA0 + aoff,      sa);
        CP_ASYNC16(dstA0 + aoff + 16, sa + 4);
        CP_ASYNC16(dstA0 + aoff + 32, sa + 8);
        CP_ASYNC16(dstA0 + aoff + 48, sa + 12);
        const uint32_t* sb = srcB0 + kc * 32;
        CP_ASYNC16(dstB0 + boff,      sb);
        CP_ASYNC16(dstB0 + boff + 16, sb + 4);
        CP_ASYNC16(dstB0 + boff + 32, sb + 8);
        CP_ASYNC16(dstB0 + boff + 48, sb + 12);
        CP_COMMIT();
    };

    const int KT = HIDN / BKF;   // 32
    issue(0, 0); issue(1, 1);

    int stg = 0;
    for (int kt = 0; kt < KT; kt++) {
        CP_WAIT(1);
        __syncthreads();
        if (kt + 2 < KT) {
            int s = stg + 2; if (s >= NSTG) s -= NSTG;
            issue(s, kt + 2);
        }

        uint32_t sA = aBase + stg * A_STG * 4;
        uint32_t sB = bBase + stg * B_STG * 4;
#pragma unroll
        for (int kk = 0; kk < 4; kk++) {
            uint32_t koff = kk * 32;
            uint32_t a[2][4];
#pragma unroll
            for (int i = 0; i < 2; i++)
                LDSM_X4(a[i][0], a[i][1], a[i][2], a[i][3],
                        sA + i * (16 * PADU * 4) + koff);
            uint32_t bv[4][4];
#pragma unroll
            for (int jp = 0; jp < 4; jp++)
                LDSM_X4(bv[jp][0], bv[jp][1], bv[jp][2], bv[jp][3],
                        sB + jp * (16 * PADU * 4) + koff);
#pragma unroll
            for (int i = 0; i < 2; i++)
#pragma unroll
                for (int j = 0; j < 8; j++)
                    mma_f16(acc[i][j], a[i], &bv[j >> 1][(j & 1) * 2]);
        }
        if (++stg >= NSTG) stg = 0;
    }
    CP_WAIT(0);

#pragma unroll
    for (int i = 0; i < 2; i++) {
#pragma unroll
        for (int half = 0; half < 2; half++) {
            int rloc = wm * 32 + i * 16 + q + half * 8;
            if (mb * 128 + rloc < cnt) {
                float* prow = g_P + (size_t)(base + rloc) * DIMN + n0;
#pragma unroll
                for (int j = 0; j < 8; j++) {
                    int cl = wn * 64 + j * 8 + t4 * 2;
                    *reinterpret_cast<float2*>(&prow[cl]) =
                        make_float2(acc[i][j][half * 2 + 0], acc[i][j][half * 2 + 1]);
                }
            }
        }
    }
}

// ============================ 6: combine ============================
__global__ void combine_kernel(float* __restrict__ y) {
    size_t idx = (size_t)blockIdx.x * blockDim.x + threadIdx.x;
    if (idx >= (size_t)T_TOK * DIMN / 4) return;
    int t = (int)(idx / (DIMN / 4));
    int d4 = (int)(idx % (DIMN / 4)) * 4;
    int s0 = g_slot[2 * t], s1 = g_slot[2 * t + 1];
    float w0 = g_wt[s0], w1 = g_wt[s1];
    float4 p0 = *reinterpret_cast<const float4*>(&g_P[(size_t)s0 * DIMN + d4]);
    float4 p1 = *reinterpret_cast<const float4*>(&g_P[(size_t)s1 * DIMN + d4]);
    float4 r;
    r.x = w0 * p0.x + w1 * p1.x;
    r.y = w0 * p0.y + w1 * p1.y;
    r.z = w0 * p0.z + w1 * p1.z;
    r.w = w0 * p0.w + w1 * p1.w;
    *reinterpret_cast<float4*>(&y[(size_t)t * DIMN + d4]) = r;
}

// ============================ launch ============================
extern "C" void kernel_launch(void* const* d_in, const int* in_sizes, int n_in,
                              void* d_out, int out_size) {
    const float* x  = (const float*)d_in[0];
    const float* wg = (const float*)d_in[1];
    const float* w1 = (const float*)d_in[2];
    const float* w2 = (const float*)d_in[3];
    const float* w3 = (const float*)d_in[4];
    float* y = (float*)d_out;

    const int smem1 = NSTG * (128 + 64 + 64) * PADU * 4;   // 110592
    const int smem2 = NSTG * (128 + 128) * PADU * 4;       // 110592
    cudaFuncSetAttribute(ffn1_kernel, cudaFuncAttributeMaxDynamicSharedMemorySize, smem1);
    cudaFuncSetAttribute(ffn2_kernel, cudaFuncAttributeMaxDynamicSharedMemorySize, smem2);

    convw_kernel<<<8192 + 16384, 256>>>(w1, w2, w3);
    gate_kernel<<<T_TOK / 8, 256>>>(x, wg);
    gather_kernel<<<(int)(((size_t)T_TOK * 2 * (DIMN / 8) + 255) / 256), 256>>>(x);
    ffn1_kernel<<<dim3(HIDN / 64, T_TOK / 128, NE), 256, smem1>>>();
    ffn2_kernel<<<dim3(DIMN / 128, T_TOK / 128, NE), 256, smem2>>>();
    combine_kernel<<<(T_TOK * DIMN / 4 + 255) / 256, 256>>>(y);
}

// round 14
// speedup vs baseline: 1.1601x; 1.1601x over previous
#include <cuda_runtime.h>
#include <cuda_fp16.h>
#include <cstdint>
#include <math.h>

#define T_TOK 16384
#define DIMN  1024
#define HIDN  2048
#define NE    8

#define BKF   32     // fp16 elements of K per stage
#define PADU  20     // smem row stride in u32 (16 payload + 4 pad)
#define NSTG  4

// ============================ helpers ============================
#define CP_ASYNC16(dst, src) asm volatile("cp.async.cg.shared.global [%0], [%1], 16;" :: "r"(dst), "l"(src))
#define CP_COMMIT()          asm volatile("cp.async.commit_group;" ::: "memory")
#define CP_WAIT(n)           asm volatile("cp.async.wait_group %0;" :: "n"(n) : "memory")

#define LDSM_X4(r0, r1, r2, r3, addr) \
    asm volatile("ldmatrix.sync.aligned.m8n8.x4.shared.b16 {%0,%1,%2,%3}, [%4];" \
        : "=r"(r0), "=r"(r1), "=r"(r2), "=r"(r3) : "r"(addr))

__device__ __forceinline__ uint32_t smem_u32(const void* p) {
    uint32_t a;
    asm("{ .reg .u64 t; cvta.to.shared.u64 t, %1; cvt.u32.u64 %0, t; }" : "=r"(a) : "l"(p));
    return a;
}
__device__ __forceinline__ uint32_t pack_h2(float lo, float hi) {
    __half2 h = __floats2half2_rn(lo, hi);
    return *reinterpret_cast<uint32_t*>(&h);
}
__device__ __forceinline__ void mma_f16(float* c, const uint32_t* a, const uint32_t* b) {
    asm volatile(
        "mma.sync.aligned.m16n8k16.row.col.f32.f16.f16.f32 "
        "{%0,%1,%2,%3}, {%4,%5,%6,%7}, {%8,%9}, {%0,%1,%2,%3};"
        : "+f"(c[0]), "+f"(c[1]), "+f"(c[2]), "+f"(c[3])
        : "r"(a[0]), "r"(a[1]), "r"(a[2]), "r"(a[3]), "r"(b[0]), "r"(b[1]));
}

// ============================ device scratch (fixed-capacity dispatch) ============================
__device__ int      g_count[NE];
__device__ float    g_wt  [NE * T_TOK];
__device__ int      g_slot[T_TOK * 2];
__device__ uint32_t g_Xh [(size_t)NE * T_TOK * DIMN / 2];   // fp16 pairs, capacity slots
__device__ uint32_t g_Hh [(size_t)NE * T_TOK * HIDN / 2];   // fp16 pairs
__device__ uint32_t g_Ph [(size_t)NE * T_TOK * DIMN / 2];   // WEIGHTED partials, fp16 pairs
__device__ uint32_t g_w1h[(size_t)NE * HIDN * DIMN / 2];    // fp16 pairs [e][n][k/2]
__device__ uint32_t g_w3h[(size_t)NE * HIDN * DIMN / 2];
__device__ uint32_t g_w2h[(size_t)NE * DIMN * HIDN / 2];    // transposed [e][n(dim)][k(hid)/2]

// ============================ 1: fused weight conversion (+count reset) ============================
__global__ void convw_kernel(const float* __restrict__ w1, const float* __restrict__ w2,
                             const float* __restrict__ w3) {
    if (blockIdx.x == 0 && threadIdx.x < NE) g_count[threadIdx.x] = 0;

    if (blockIdx.x < 8192) {
        size_t idx = (size_t)blockIdx.x * 256 + threadIdx.x;
        size_t o = idx * 8;
        {
            float4 v0 = *reinterpret_cast<const float4*>(&w1[o]);
            float4 v1 = *reinterpret_cast<const float4*>(&w1[o + 4]);
            uint4 u;
            u.x = pack_h2(v0.x, v0.y); u.y = pack_h2(v0.z, v0.w);
            u.z = pack_h2(v1.x, v1.y); u.w = pack_h2(v1.z, v1.w);
            *reinterpret_cast<uint4*>(&g_w1h[o / 2]) = u;
        }
        {
            float4 v0 = *reinterpret_cast<const float4*>(&w3[o]);
            float4 v1 = *reinterpret_cast<const float4*>(&w3[o + 4]);
            uint4 u;
            u.x = pack_h2(v0.x, v0.y); u.y = pack_h2(v0.z, v0.w);
            u.z = pack_h2(v1.x, v1.y); u.w = pack_h2(v1.z, v1.w);
            *reinterpret_cast<uint4*>(&g_w3h[o / 2]) = u;
        }
    } else {
        __shared__ float tile[32][33];
        int b2 = blockIdx.x - 8192;
        int e = b2 >> 11;
        int rem = b2 & 2047;
        int k0 = (rem >> 5) * 32;
        int n0 = (rem & 31) * 32;
        int tx = threadIdx.x & 31, ty = threadIdx.x >> 5;
        const float* wp = w2 + (size_t)e * HIDN * DIMN;
#pragma unroll
        for (int i = 0; i < 4; i++)
            tile[ty + 8 * i][tx] = wp[(size_t)(k0 + ty + 8 * i) * DIMN + n0 + tx];
        __syncthreads();
        int row = threadIdx.x >> 3;
        int cu = threadIdx.x & 7;
        uint32_t* op = &g_w2h[((size_t)e * DIMN + n0 + row) * (HIDN / 2) + k0 / 2];
#pragma unroll
        for (int jj = 0; jj < 2; jj++) {
            int j = cu * 2 + jj;
            op[j] = pack_h2(tile[2 * j][row], tile[2 * j + 1][row]);
        }
    }
}

// ============================ 2: gate + fused fp16 gather ============================
__global__ void gate_kernel(const float* __restrict__ x, const float* __restrict__ wg) {
    int warp = threadIdx.x >> 5, lane = threadIdx.x & 31;
    int t = blockIdx.x * 8 + warp;
    if (t >= T_TOK) return;
    float acc[NE];
#pragma unroll
    for (int e = 0; e < NE; e++) acc[e] = 0.f;
    const float* xr = x + (size_t)t * DIMN;
    for (int d = lane; d < DIMN; d += 32) {
        float xv = xr[d];
#pragma unroll
        for (int e = 0; e < NE; e++) acc[e] += xv * wg[d * NE + e];
    }
#pragma unroll
    for (int e = 0; e < NE; e++)
#pragma unroll
        for (int o = 16; o > 0; o >>= 1) acc[e] += __shfl_xor_sync(0xffffffffu, acc[e], o);

    int s0 = 0, s1 = 0;
    if (lane == 0) {
        int i0 = 0; float l0 = acc[0];
#pragma unroll
        for (int e = 1; e < NE; e++) if (acc[e] > l0) { l0 = acc[e]; i0 = e; }
        int i1 = -1; float l1 = -3.0e38f;
#pragma unroll
        for (int e = 0; e < NE; e++) if (e != i0 && acc[e] > l1) { l1 = acc[e]; i1 = e; }
        float w0 = 1.f / (1.f + expf(l1 - l0));
        int p0 = atomicAdd(&g_count[i0], 1);
        s0 = i0 * T_TOK + p0;
        g_wt[s0] = w0;
        g_slot[2 * t] = s0;
        int p1 = atomicAdd(&g_count[i1], 1);
        s1 = i1 * T_TOK + p1;
        g_wt[s1] = 1.f - w0;
        g_slot[2 * t + 1] = s1;
    }
    s0 = __shfl_sync(0xffffffffu, s0, 0);
    s1 = __shfl_sync(0xffffffffu, s1, 0);

    // fused gather: pack row t to fp16 pairs, write to both capacity slots
    uint32_t* d0 = &g_Xh[(size_t)s0 * (DIMN / 2)];
    uint32_t* d1 = &g_Xh[(size_t)s1 * (DIMN / 2)];
#pragma unroll
    for (int it = 0; it < DIMN / 2 / 32; it++) {
        int u = it * 32 + lane;
        float2 v = *reinterpret_cast<const float2*>(&xr[2 * u]);
        uint32_t p = pack_h2(v.x, v.y);
        d0[u] = p;
        d1[u] = p;
    }
}

// ============================ 3: ffn1  H = silu(X W1^T) * (X W3^T) ============================
// BM=128 BN=64 BK=32. 256 threads, 8 warps 4(m)x2(n); warp tile 32x32 dual. ldmatrix.
// NSTG=4, prefetch 3, CP_WAIT(2), single sync per round.
__global__ void __launch_bounds__(256, 2) ffn1_kernel() {
    int e = blockIdx.z;
    int cnt = g_count[e];
    int mb = blockIdx.y;
    if (mb * 128 >= cnt) return;
    int base = e * T_TOK + mb * 128;
    int n0 = blockIdx.x * 64;

    extern __shared__ uint32_t smem[];
    uint32_t* As  = smem;                        // [NSTG][128*PADU]
    uint32_t* B1s = As  + NSTG * 128 * PADU;     // [NSTG][64*PADU]
    uint32_t* B3s = B1s + NSTG * 64 * PADU;      // [NSTG][64*PADU]
    const int A_STG = 128 * PADU, B_STG = 64 * PADU;

    int tid = threadIdx.x, wid = tid >> 5, lane = tid & 31;
    int wm = wid & 3, wn = wid >> 2;
    int q = lane >> 2, t4 = lane & 3;

    int arowL = tid >> 1, apart = tid & 1;
    const uint32_t* srcA0 = g_Xh + (size_t)(base + arowL) * (DIMN / 2) + apart * 8;
    uint32_t dstA0 = smem_u32(&As[arowL * PADU + apart * 8]);

    int browL = (tid & 127) >> 1, bpart = tid & 1, bmat = tid >> 7;
    const uint32_t* srcB0 = (bmat ? g_w3h : g_w1h)
        + ((size_t)e * HIDN + n0 + browL) * (DIMN / 2) + bpart * 8;
    uint32_t dstB0 = smem_u32((bmat ? B3s : B1s) + browL * PADU + bpart * 8);

    uint32_t aBase = smem_u32(As) + (((wm * 32 + (lane & 15)) * PADU) + (lane >> 4) * 4) * 4;
    uint32_t bRow = wn * 32 + (lane & 7) + ((lane >> 4) & 1) * 8;
    uint32_t bCol = ((lane >> 3) & 1) * 4;
    uint32_t b1Base = smem_u32(B1s) + ((bRow * PADU) + bCol) * 4;
    uint32_t b3Base = smem_u32(B3s) + ((bRow * PADU) + bCol) * 4;

    float acc1[2][4][4], acc3[2][4][4];
#pragma unroll
    for (int i = 0; i < 2; i++)
#pragma unroll
        for (int j = 0; j < 4; j++)
#pragma unroll
            for (int v = 0; v < 4; v++) { acc1[i][j][v] = 0.f; acc3[i][j][v] = 0.f; }

    auto issue = [&](int s, int kc) {
        uint32_t aoff = (uint32_t)(s * A_STG * 4);
        uint32_t boff = (uint32_t)(s * B_STG * 4);
        const uint32_t* sa = srcA0 + kc * 16;
        CP_ASYNC16(dstA0 + aoff, sa); CP_ASYNC16(dstA0 + aoff + 16, sa + 4);
        const uint32_t* sb = srcB0 + kc * 16;
        CP_ASYNC16(dstB0 + boff, sb); CP_ASYNC16(dstB0 + boff + 16, sb + 4);
        CP_COMMIT();
    };

    const int KT = DIMN / BKF;   // 32
    issue(0, 0); issue(1, 1); issue(2, 2);

    for (int kt = 0; kt < KT; kt++) {
        int stg = kt & 3;
        CP_WAIT(2);
        __syncthreads();
        if (kt + 3 < KT) issue((kt + 3) & 3, kt + 3);

        uint32_t sA = aBase + stg * A_STG * 4;
        uint32_t sB1 = b1Base + stg * B_STG * 4;
        uint32_t sB3 = b3Base + stg * B_STG * 4;
#pragma unroll
        for (int kk = 0; kk < 2; kk++) {
            uint32_t koff = kk * 32;
            uint32_t a[2][4];
#pragma unroll
            for (int i = 0; i < 2; i++)
                LDSM_X4(a[i][0], a[i][1], a[i][2], a[i][3],
                        sA + i * (16 * PADU * 4) + koff);
            uint32_t b1v[2][4], b3v[2][4];
#pragma unroll
            for (int jp = 0; jp < 2; jp++) {
                LDSM_X4(b1v[jp][0], b1v[jp][1], b1v[jp][2], b1v[jp][3],
                        sB1 + jp * (16 * PADU * 4) + koff);
                LDSM_X4(b3v[jp][0], b3v[jp][1], b3v[jp][2], b3v[jp][3],
                        sB3 + jp * (16 * PADU * 4) + koff);
            }
#pragma unroll
            for (int i = 0; i < 2; i++)
#pragma unroll
                for (int j = 0; j < 4; j++) {
                    mma_f16(acc1[i][j], a[i], &b1v[j >> 1][(j & 1) * 2]);
                    mma_f16(acc3[i][j], a[i], &b3v[j >> 1][(j & 1) * 2]);
                }
        }
    }
    CP_WAIT(0);

    // epilogue: h = silu(z1)*z3, store fp16 pairs
#pragma unroll
    for (int i = 0; i < 2; i++) {
#pragma unroll
        for (int half = 0; half < 2; half++) {
            int rloc = wm * 32 + i * 16 + q + half * 8;
            if (mb * 128 + rloc < cnt) {
                uint32_t* hrow = g_Hh + (size_t)(base + rloc) * (HIDN / 2) + n0 / 2;
#pragma unroll
                for (int j = 0; j < 4; j++) {
                    int cl = wn * 32 + j * 8 + t4 * 2;
                    float z0 = acc1[i][j][half * 2 + 0];
                    float z1 = acc1[i][j][half * 2 + 1];
                    float h0 = z0 / (1.f + __expf(-z0)) * acc3[i][j][half * 2 + 0];
                    float h1 = z1 / (1.f + __expf(-z1)) * acc3[i][j][half * 2 + 1];
                    hrow[cl / 2] = pack_h2(h0, h1);
                }
            }
        }
    }
}

// ============================ 4: ffn2  P = w * (H W2), fp16 out ============================
// BM=128 BN=128 BK=32. 256 threads, 8 warps 4(m)x2(n); warp tile 32x64. ldmatrix.
__global__ void __launch_bounds__(256, 2) ffn2_kernel() {
    int e = blockIdx.z;
    int cnt = g_count[e];
    int mb = blockIdx.y;
    if (mb * 128 >= cnt) return;
    int base = e * T_TOK + mb * 128;
    int n0 = blockIdx.x * 128;

    extern __shared__ uint32_t smem[];
    uint32_t* As = smem;                         // [NSTG][128*PADU]
    uint32_t* Bs = As + NSTG * 128 * PADU;       // [NSTG][128*PADU]
    const int A_STG = 128 * PADU, B_STG = 128 * PADU;

    int tid = threadIdx.x, wid = tid >> 5, lane = tid & 31;
    int wm = wid & 3, wn = wid >> 2;
    int q = lane >> 2, t4 = lane & 3;

    int arowL = tid >> 1, apart = tid & 1;
    const uint32_t* srcA0 = g_Hh + (size_t)(base + arowL) * (HIDN / 2) + apart * 8;
    uint32_t dstA0 = smem_u32(&As[arowL * PADU + apart * 8]);

    int browL = tid >> 1, bpart = tid & 1;
    const uint32_t* srcB0 = g_w2h + ((size_t)e * DIMN + n0 + browL) * (HIDN / 2) + bpart * 8;
    uint32_t dstB0 = smem_u32(&Bs[browL * PADU + bpart * 8]);

    uint32_t aBase = smem_u32(As) + (((wm * 32 + (lane & 15)) * PADU) + (lane >> 4) * 4) * 4;
    uint32_t bRow = wn * 64 + (lane & 7) + ((lane >> 4) & 1) * 8;
    uint32_t bCol = ((lane >> 3) & 1) * 4;
    uint32_t bBase = smem_u32(Bs) + ((bRow * PADU) + bCol) * 4;

    float acc[2][8][4];
#pragma unroll
    for (int i = 0; i < 2; i++)
#pragma unroll
        for (int j = 0; j < 8; j++)
#pragma unroll
            for (int v = 0; v < 4; v++) acc[i][j][v] = 0.f;

    auto issue = [&](int s, int kc) {
        uint32_t aoff = (uint32_t)(s * A_STG * 4);
        uint32_t boff = (uint32_t)(s * B_STG * 4);
        const uint32_t* sa = srcA0 + kc * 16;
        CP_ASYNC16(dstA0 + aoff, sa); CP_ASYNC16(dstA0 + aoff + 16, sa + 4);
        const uint32_t* sb = srcB0 + kc * 16;
        CP_ASYNC16(dstB0 + boff, sb); CP_ASYNC16(dstB0 + boff + 16, sb + 4);
        CP_COMMIT();
    };

    const int KT = HIDN / BKF;   // 64
    issue(0, 0); issue(1, 1); issue(2, 2);

    for (int kt = 0; kt < KT; kt++) {
        int stg = kt & 3;
        CP_WAIT(2);
        __syncthreads();
        if (kt + 3 < KT) issue((kt + 3) & 3, kt + 3);

        uint32_t sA = aBase + stg * A_STG * 4;
        uint32_t sB = bBase + stg * B_STG * 4;
#pragma unroll
        for (int kk = 0; kk < 2; kk++) {
            uint32_t koff = kk * 32;
            uint32_t a[2][4];
#pragma unroll
            for (int i = 0; i < 2; i++)
                LDSM_X4(a[i][0], a[i][1], a[i][2], a[i][3],
                        sA + i * (16 * PADU * 4) + koff);
            uint32_t bv[4][4];
#pragma unroll
            for (int jp = 0; jp < 4; jp++)
                LDSM_X4(bv[jp][0], bv[jp][1], bv[jp][2], bv[jp][3],
                        sB + jp * (16 * PADU * 4) + koff);
#pragma unroll
            for (int i = 0; i < 2; i++)
#pragma unroll
                for (int j = 0; j < 8; j++)
                    mma_f16(acc[i][j], a[i], &bv[j >> 1][(j & 1) * 2]);
        }
    }
    CP_WAIT(0);

    // epilogue: weight by routing weight, store fp16 pairs
#pragma unroll
    for (int i = 0; i < 2; i++) {
#pragma unroll
        for (int half = 0; half < 2; half++) {
            int rloc = wm * 32 + i * 16 + q + half * 8;
            if (mb * 128 + rloc < cnt) {
                float w = g_wt[base + rloc];
                uint32_t* prow = g_Ph + (size_t)(base + rloc) * (DIMN / 2) + n0 / 2;
#pragma unroll
                for (int j = 0; j < 8; j++) {
                    int cl = wn * 64 + j * 8 + t4 * 2;
                    prow[cl / 2] = pack_h2(w * acc[i][j][half * 2 + 0],
                                           w * acc[i][j][half * 2 + 1]);
                }
            }
        }
    }
}

// ============================ 5: combine (fp16 weighted partials -> fp32 y) ============================
__global__ void combine_kernel(float* __restrict__ y) {
    size_t idx = (size_t)blockIdx.x * blockDim.x + threadIdx.x;   // over T*DIM/8
    if (idx >= (size_t)T_TOK * DIMN / 8) return;
    int t = (int)(idx / (DIMN / 8));
    int u4 = (int)(idx % (DIMN / 8)) * 4;      // u32 index (4 u32 = 8 halves)
    int s0 = g_slot[2 * t], s1 = g_slot[2 * t + 1];
    uint4 p0 = *reinterpret_cast<const uint4*>(&g_Ph[(size_t)s0 * (DIMN / 2) + u4]);
    uint4 p1 = *reinterpret_cast<const uint4*>(&g_Ph[(size_t)s1 * (DIMN / 2) + u4]);
    const uint32_t* a = &p0.x;
    const uint32_t* b = &p1.x;
    float out[8];
#pragma unroll
    for (int j = 0; j < 4; j++) {
        __half2 ha = *reinterpret_cast<const __half2*>(&a[j]);
        __half2 hb = *reinterpret_cast<const __half2*>(&b[j]);
        float2 fa = __half22float2(ha);
        float2 fb = __half22float2(hb);
        out[2 * j]     = fa.x + fb.x;
        out[2 * j + 1] = fa.y + fb.y;
    }
    float* yo = &y[(size_t)t * DIMN + u4 * 2];
    *reinterpret_cast<float4*>(yo)     = *reinterpret_cast<float4*>(&out[0]);
    *reinterpret_cast<float4*>(yo + 4) = *reinterpret_cast<float4*>(&out[4]);
}

// ============================ launch ============================
extern "C" void kernel_launch(void* const* d_in, const int* in_sizes, int n_in,
                              void* d_out, int out_size) {
    const float* x  = (const float*)d_in[0];
    const float* wg = (const float*)d_in[1];
    const float* w1 = (const float*)d_in[2];
    const float* w2 = (const float*)d_in[3];
    const float* w3 = (const float*)d_in[4];
    float* y = (float*)d_out;

    const int smem1 = NSTG * (128 + 64 + 64) * PADU * 4;   // 81920
    const int smem2 = NSTG * (128 + 128) * PADU * 4;       // 81920
    cudaFuncSetAttribute(ffn1_kernel, cudaFuncAttributeMaxDynamicSharedMemorySize, smem1);
    cudaFuncSetAttribute(ffn2_kernel, cudaFuncAttributeMaxDynamicSharedMemorySize, smem2);

    convw_kernel<<<8192 + 16384, 256>>>(w1, w2, w3);
    gate_kernel<<<T_TOK / 8, 256>>>(x, wg);
    ffn1_kernel<<<dim3(HIDN / 64, T_TOK / 128, NE), 256, smem1>>>();
    ffn2_kernel<<<dim3(DIMN / 128, T_TOK / 128, NE), 256, smem2>>>();
    combine_kernel<<<(int)(((size_t)T_TOK * DIMN / 8 + 255) / 256), 256>>>(y);
}